// round 15
// baseline (speedup 1.0000x reference)
#include <cuda_runtime.h>
#include <cuda_fp16.h>
#include <math.h>

#define T_TOKENS 16384
#define N_EXP    256
#define HID      7168
#define NGROUP   8
#define TOPKG    4
#define TOPK     8

#define BLK_M    128
#define BLK_N    64
#define BK       32
#define NSTAGES  224           // HID / BK
#define STAGE_BYTES 24576      // Ah 8192 | Am 8192 | Bh 4096 | Bm 4096
#define SMEM_TOTAL 49152

typedef unsigned int u32;

// static device scratch (allowed)
__device__ __half g_Wh[(size_t)HID * N_EXP];     // W transposed, high limb  [k][n]
__device__ __half g_Wm[(size_t)HID * N_EXP];     // W transposed, low  limb  [k][n]
__device__ float  g_logits[(size_t)T_TOKENS * N_EXP];

// ---------------------------------------------------------------------------
__device__ __forceinline__ u32 smem_u32(const void* p) {
    u32 r;
    asm("{ .reg .u64 t; cvta.to.shared.u64 t, %1; cvt.u32.u64 %0, t; }" : "=r"(r) : "l"(p));
    return r;
}

__device__ __forceinline__ void ldmA(u32* r, u32 addr) {
    asm volatile("ldmatrix.sync.aligned.m8n8.x4.shared.b16 {%0,%1,%2,%3}, [%4];"
                 : "=r"(r[0]), "=r"(r[1]), "=r"(r[2]), "=r"(r[3]) : "r"(addr));
}
__device__ __forceinline__ void ldmBT(u32* r, u32 addr) {
    asm volatile("ldmatrix.sync.aligned.m8n8.x4.trans.shared.b16 {%0,%1,%2,%3}, [%4];"
                 : "=r"(r[0]), "=r"(r[1]), "=r"(r[2]), "=r"(r[3]) : "r"(addr));
}
__device__ __forceinline__ void mma16816(float* c, const u32* a, const u32* b) {
    asm volatile(
        "mma.sync.aligned.m16n8k16.row.col.f32.f16.f16.f32 "
        "{%0,%1,%2,%3}, {%4,%5,%6,%7}, {%8,%9}, {%0,%1,%2,%3};"
        : "+f"(c[0]), "+f"(c[1]), "+f"(c[2]), "+f"(c[3])
        : "r"(a[0]), "r"(a[1]), "r"(a[2]), "r"(a[3]), "r"(b[0]), "r"(b[1]));
}
__device__ __forceinline__ void cp16(u32 dst, const void* src) {
    asm volatile("cp.async.cg.shared.global [%0], [%1], 16;" :: "r"(dst), "l"(src) : "memory");
}

// split 16 fp32 -> 8x u32 high-limb pairs + 8x u32 low-limb pairs
// Packed-cvt version: bit-identical results to the scalar version
// (__float22half2_rn = RN per element == __float2half_rn; exact up-cvt; exact sub)
// but ~6 instrs/pair instead of ~10 -> relieves cvt/fma pipe pressure.
__device__ __forceinline__ void split16(const float4* v, u32* H, u32* M) {
    const float* x = (const float*)v;
#pragma unroll
    for (int i = 0; i < 8; ++i) {
        float2 ab = make_float2(x[2 * i], x[2 * i + 1]);
        __half2 hh = __float22half2_rn(ab);            // 1 packed down-cvt
        float2  hu = __half22float2(hh);               // 2 up-cvt (exact)
        __half2 mm = __floats2half2_rn(ab.x - hu.x,    // 2 FADD + 1 packed down-cvt
                                       ab.y - hu.y);
        H[i] = *(u32*)&hh;
        M[i] = *(u32*)&mm;
    }
}

// ---------------------------------------------------------------------------
// Phase 0: W -> transposed fp16 limb arrays Wt[k][n]
// ---------------------------------------------------------------------------
__global__ __launch_bounds__(256) void w_convert(const float* __restrict__ W) {
    const int k = blockIdx.x;        // 0..7167
    const int e = threadIdx.x;       // 0..255
    float x = W[(size_t)e * HID + k];
    __half h = __float2half_rn(x);
    __half m = __float2half_rn(x - __half2float(h));
    g_Wh[(size_t)k * N_EXP + e] = h;
    g_Wm[(size_t)k * N_EXP + e] = m;
}

// ---------------------------------------------------------------------------
// Phase 1: fp16x2-limb HMMA GEMM.  logits[t,e] = sum_k A[t,k] W[e,k]
// CTA 128x64, 8 warps (4m x 2n), warp 32x32, BK=32, double buffered.
// Terms: hh (+ hm + mh); two-level accumulation (fold every 16 stages).
// Occupancy 2 (4 warps/SMSP). split16 uses packed cvts (bit-identical).
// Expected rel_err exactly 4.299034e-4 (logits bit-identical to R14 run).
// ---------------------------------------------------------------------------
__global__ __launch_bounds__(256, 2) void router_hmma(const float* __restrict__ A) {
    extern __shared__ char smem[];
    const u32 sbase = smem_u32(smem);
    const int tid = threadIdx.x, lane = tid & 31, wid = tid >> 5;
    const int wm = wid & 3, wn = wid >> 2;

    float mast[2][4][4], chk[2][4][4];
#pragma unroll
    for (int i = 0; i < 2; ++i)
#pragma unroll
        for (int j = 0; j < 4; ++j)
#pragma unroll
            for (int q = 0; q < 4; ++q) { mast[i][j][q] = 0.f; chk[i][j][q] = 0.f; }

    // A staging: thread -> (row am, 16-float half ah)
    const int am = tid >> 1;
    const int ah = tid & 1;
    const float* Aptr = A + (size_t)(blockIdx.x * BLK_M + am) * HID + ah * 16;
    const u32 asts0 = (u32)am * 64 + (u32)((((ah * 2 + 0) ^ (am & 3))) * 16);
    const u32 asts1 = (u32)am * 64 + (u32)((((ah * 2 + 1) ^ (am & 3))) * 16);

    // B staging: thread -> (k row bk, 16B chunk bnc)
    const int bk = tid >> 3;
    const int bnc = tid & 7;
    const int n0 = blockIdx.y * BLK_N;
    const __half* WhP = g_Wh + (size_t)bk * N_EXP + n0 + bnc * 8;
    const __half* WmP = g_Wm + (size_t)bk * N_EXP + n0 + bnc * 8;
    const u32 bswz = (u32)bk * 128 + (u32)((bnc ^ (bk & 7)) * 16);
    const size_t wstride = (size_t)BK * N_EXP;   // halves per stage

    // ---- prologue: stage 0 ----
    float4 ar[4];
    {
        cp16(sbase + 16384 + bswz, WhP);
        cp16(sbase + 20480 + bswz, WmP);
        asm volatile("cp.async.commit_group;" ::: "memory");
#pragma unroll
        for (int i = 0; i < 4; ++i) ar[i] = *(const float4*)(Aptr + i * 4);
        u32 H[8], M[8];
        split16(ar, H, M);
        *(uint4*)(smem + asts0) = make_uint4(H[0], H[1], H[2], H[3]);
        *(uint4*)(smem + asts1) = make_uint4(H[4], H[5], H[6], H[7]);
        *(uint4*)(smem + 8192 + asts0) = make_uint4(M[0], M[1], M[2], M[3]);
        *(uint4*)(smem + 8192 + asts1) = make_uint4(M[4], M[5], M[6], M[7]);
    }

    const int arow = lane & 15, asel = lane >> 4;
    const int kl = (lane & 7) + (lane & 8);
    const int bsel = lane >> 4;

    for (int s = 0; s < NSTAGES; ++s) {
        const int cur = s & 1;
        asm volatile("cp.async.wait_group 0;" ::: "memory");
        __syncthreads();

        const u32 nbase = sbase + (cur ^ 1) * STAGE_BYTES;
        if (s + 1 < NSTAGES) {
            cp16(nbase + 16384 + bswz, WhP + (size_t)(s + 1) * wstride);
            cp16(nbase + 20480 + bswz, WmP + (size_t)(s + 1) * wstride);
            asm volatile("cp.async.commit_group;" ::: "memory");
            const float* ap = Aptr + (s + 1) * BK;
#pragma unroll
            for (int i = 0; i < 4; ++i) ar[i] = *(const float4*)(ap + i * 4);
        }

        // ---- compute stage cur ----
        {
            const u32 sA = sbase + cur * STAGE_BYTES;
#pragma unroll
            for (int k16 = 0; k16 < 2; ++k16) {
                u32 fah[2][4], fam[2][4], bh[4][2], bm[4][2];
#pragma unroll
                for (int mt = 0; mt < 2; ++mt) {
                    int ml = wm * 32 + mt * 16 + arow;
                    u32 off = (u32)ml * 64 + (u32)((((k16 * 2 + asel) ^ (arow & 3))) * 16);
                    ldmA(fah[mt], sA + off);
                    ldmA(fam[mt], sA + 8192 + off);
                }
#pragma unroll
                for (int nt = 0; nt < 2; ++nt) {
                    u32 off = (u32)(k16 * 16 + kl) * 128 +
                              (u32)((((wn * 4 + nt * 2 + bsel) ^ (lane & 7))) * 16);
                    u32 r[4];
                    ldmBT(r, sA + 16384 + off);
                    bh[nt * 2][0] = r[0]; bh[nt * 2][1] = r[1];
                    bh[nt * 2 + 1][0] = r[2]; bh[nt * 2 + 1][1] = r[3];
                    ldmBT(r, sA + 20480 + off);
                    bm[nt * 2][0] = r[0]; bm[nt * 2][1] = r[1];
                    bm[nt * 2 + 1][0] = r[2]; bm[nt * 2 + 1][1] = r[3];
                }
#pragma unroll
                for (int mt = 0; mt < 2; ++mt)
#pragma unroll
                    for (int t = 0; t < 4; ++t) {
                        mma16816(chk[mt][t], fah[mt], bh[t]);   // hh
                        mma16816(chk[mt][t], fah[mt], bm[t]);   // hm
                        mma16816(chk[mt][t], fam[mt], bh[t]);   // mh
                    }
            }
        }

        // ---- stage s+1 A convert + STS ----
        if (s + 1 < NSTAGES) {
            u32 H[8], M[8];
            split16(ar, H, M);
            char* nb = smem + (cur ^ 1) * STAGE_BYTES;
            *(uint4*)(nb + asts0) = make_uint4(H[0], H[1], H[2], H[3]);
            *(uint4*)(nb + asts1) = make_uint4(H[4], H[5], H[6], H[7]);
            *(uint4*)(nb + 8192 + asts0) = make_uint4(M[0], M[1], M[2], M[3]);
            *(uint4*)(nb + 8192 + asts1) = make_uint4(M[4], M[5], M[6], M[7]);
        }

        // ---- two-level accumulation fold (every 16 stages = K 512) ----
        if ((s & 15) == 15) {
#pragma unroll
            for (int i = 0; i < 2; ++i)
#pragma unroll
                for (int j = 0; j < 4; ++j)
#pragma unroll
                    for (int q = 0; q < 4; ++q) {
                        mast[i][j][q] += chk[i][j][q];
                        chk[i][j][q] = 0.f;
                    }
        }
    }

    // ---- epilogue ----
    const int g = lane >> 2, qp = (lane & 3) * 2;
#pragma unroll
    for (int mt = 0; mt < 2; ++mt)
#pragma unroll
        for (int t = 0; t < 4; ++t) {
            int token = blockIdx.x * BLK_M + wm * 32 + mt * 16 + g;
            int e = blockIdx.y * BLK_N + wn * 32 + t * 8 + qp;
            float* p = g_logits + (size_t)token * N_EXP + e;
            *(float2*)p = make_float2(mast[mt][t][0], mast[mt][t][1]);
            *(float2*)(p + 8 * N_EXP) = make_float2(mast[mt][t][2], mast[mt][t][3]);
        }
}

// ---------------------------------------------------------------------------
// Phase 2: grouped top-k. One warp per token.
// ---------------------------------------------------------------------------
__global__ __launch_bounds__(256) void topk_kernel(
    const float* __restrict__ bias,
    float* __restrict__ out_idx,
    float* __restrict__ out_w)
{
    __shared__ float bsh[N_EXP];
    __shared__ float s_sh[8][N_EXP];

    const int tid  = threadIdx.x;
    const int warp = tid >> 5;
    const int lane = tid & 31;
    const unsigned FULL = 0xFFFFFFFFu;

    if (tid < N_EXP) bsh[tid] = bias[tid];
    __syncthreads();

    const int token = blockIdx.x * 8 + warp;
    const float* lg = g_logits + (size_t)token * N_EXP + lane * 8;

    float c[8];
#pragma unroll
    for (int j = 0; j < 8; ++j) {
        float x = lg[j];
        float sg = 1.0f / (1.0f + expf(-x));
        c[j] = sg + bsh[lane * 8 + j];
        s_sh[warp][lane * 8 + j] = sg;
    }
    __syncwarp();

    float m1 = -INFINITY, m2 = -INFINITY;
#pragma unroll
    for (int j = 0; j < 8; ++j) {
        float v = c[j];
        if (v > m1) { m2 = m1; m1 = v; }
        else if (v > m2) { m2 = v; }
    }
#pragma unroll
    for (int off = 2; off >= 1; off >>= 1) {
        float o1 = __shfl_xor_sync(FULL, m1, off);
        float o2 = __shfl_xor_sync(FULL, m2, off);
        if (o1 > m1) { m2 = fmaxf(m1, o2); m1 = o1; }
        else         { m2 = fmaxf(m2, o1); }
    }
    float gsum = m1 + m2;

    float gs[NGROUP];
#pragma unroll
    for (int g = 0; g < NGROUP; ++g) gs[g] = __shfl_sync(FULL, gsum, g * 4);

    const int myg = lane >> 2;
    const float mys = gs[myg];
    int rank = 0;
#pragma unroll
    for (int g = 0; g < NGROUP; ++g)
        rank += (gs[g] > mys) || (gs[g] == mys && g < myg);
    const bool sel = (rank < TOPKG);

    float mc[8];
#pragma unroll
    for (int j = 0; j < 8; ++j) mc[j] = sel ? c[j] : 0.0f;

    float wsum = 0.0f;
    int   myidx = 0;
    float myw   = 0.0f;
#pragma unroll
    for (int t = 0; t < TOPK; ++t) {
        float bv = -INFINITY;
        int   bi = N_EXP;
#pragma unroll
        for (int j = 0; j < 8; ++j) {
            if (mc[j] > bv) { bv = mc[j]; bi = lane * 8 + j; }
        }
#pragma unroll
        for (int off = 16; off >= 1; off >>= 1) {
            float ov = __shfl_xor_sync(FULL, bv, off);
            int   oi = __shfl_xor_sync(FULL, bi, off);
            if (ov > bv || (ov == bv && oi < bi)) { bv = ov; bi = oi; }
        }
        float sv = s_sh[warp][bi];
        wsum += sv;
        if (lane == t) { myidx = bi; myw = sv; }
        if ((bi >> 3) == lane) {
            int jj = bi & 7;
#pragma unroll
            for (int j = 0; j < 8; ++j)
                if (j == jj) mc[j] = -INFINITY;
        }
    }

    const float scale = 2.5f / (wsum + 1e-20f);
    if (lane < TOPK) {
        out_idx[(size_t)token * TOPK + lane] = (float)myidx;
        out_w  [(size_t)token * TOPK + lane] = myw * scale;
    }
}

// ---------------------------------------------------------------------------
extern "C" void kernel_launch(void* const* d_in, const int* in_sizes, int n_in,
                              void* d_out, int out_size) {
    const float* hidden = (const float*)d_in[0];   // [16384, 7168]
    const float* weight = (const float*)d_in[1];   // [256, 7168]
    const float* bias   = (const float*)d_in[2];   // [256]
    float* out = (float*)d_out;                    // [indices | weights], fp32

    w_convert<<<HID, 256>>>(weight);
    router_hmma<<<dim3(T_TOKENS / BLK_M, N_EXP / BLK_N), 256, SMEM_TOTAL>>>(hidden);
    topk_kernel<<<T_TOKENS / 8, 256>>>(bias, out, out + (size_t)T_TOKENS * TOPK);
}